// round 1
// baseline (speedup 1.0000x reference)
#include <cuda_runtime.h>
#include <cuda_bf16.h>

#define NB 16
#define NA 49104

// ---------------- scratch (device globals; no allocation allowed) ----------------
__device__ float g_score[NB * NA];
__device__ int   g_cls[NB * NA];
__device__ float g_box[5][NB * NA];

__device__ float g_topScore[NB * 1024];
__device__ int   g_topIdx[NB * 1024];
__device__ float g_topBox[NB * 1024 * 4];

__device__ unsigned g_W[NB * 32 * 1024];  // [b][g][j] : bit b' = iou(i=g*32+b', j)>thr && i<j
__device__ unsigned g_U[NB * 32 * 32];    // [b][g][i] : intra-group transpose (row = suppressor i)

struct Ptrs { const float* p[20]; };

// ---------------- kernel 1: decode ----------------
__global__ void __launch_bounds__(256) decode_kernel(Ptrs in) {
    int t = blockIdx.x * blockDim.x + threadIdx.x;
    if (t >= NB * NA) return;
    int b = t / NA, a = t % NA;

    int l, p, h, s;
    if (a < 36864)      { l = 0; p = a;         h = 192; s = 8;   }
    else if (a < 46080) { l = 1; p = a - 36864; h = 96;  s = 16;  }
    else if (a < 48384) { l = 2; p = a - 46080; h = 48;  s = 32;  }
    else if (a < 48960) { l = 3; p = a - 48384; h = 24;  s = 64;  }
    else                { l = 4; p = a - 48960; h = 12;  s = 128; }
    int hh = h * h;

    const float* cls = in.p[l]      + b * 15 * hh + p;
    const float* reg = in.p[5 + l]  + b * 5  * hh + p;
    const float* tcp = in.p[10 + l] + b * 18 * hh + p;
    const float* trp = in.p[15 + l] + b * hh + p;

    // sigmoid is monotone -> max/argmax on logits, sigmoid once
    float best = cls[0]; int bc = 0;
#pragma unroll
    for (int c = 1; c < 15; c++) { float v = cls[c * hh]; if (v > best) { best = v; bc = c; } }
    float score = 1.0f / (1.0f + expf(-best));

    float tb = tcp[0]; int ta = 0;
#pragma unroll
    for (int c = 1; c < 18; c++) { float v = tcp[c * hh]; if (v > tb) { tb = v; ta = c; } }
    float theta = (float)(ta + 1) * 10.0f + trp[0];

    float r0 = reg[0], r1 = reg[hh], r2 = reg[2 * hh], r3 = reg[3 * hh];
    float fs = (float)s;
    int col = p % h, row = p / h;
    float x = (float)col * fs + (float)(s / 2);
    float y = (float)row * fs + (float)(s / 2);

    g_score[t] = score;
    g_cls[t]   = bc + 1;
    g_box[0][t] = x - r0 * fs;
    g_box[1][t] = y - r1 * fs;
    g_box[2][t] = x + r2 * fs;
    g_box[3][t] = y + r3 * fs;
    g_box[4][t] = theta;
}

// ---------------- kernel 2: per-batch exact top-1000 (sorted) ----------------
__global__ void __launch_bounds__(1024) topk_kernel() {
    __shared__ int hist[4096];
    __shared__ unsigned long long cand[2048];
    __shared__ int part[32];
    __shared__ int cnt, sT1, sA1, sT2;

    int b = blockIdx.x, tid = threadIdx.x;
    const float* sc = g_score + b * NA;

    for (int i = tid; i < 4096; i += 1024) hist[i] = 0;
    __syncthreads();
    for (int a = tid; a < NA; a += 1024) {
        unsigned k = __float_as_uint(sc[a]);   // scores in (0,1): positive -> bits monotone
        atomicAdd(&hist[k >> 19], 1);
    }
    __syncthreads();
    if (tid < 32) { int t2 = 0; for (int i = 0; i < 128; i++) t2 += hist[tid * 128 + i]; part[tid] = t2; }
    __syncthreads();
    if (tid == 0) {
        int target = 1000, acc = 0, T1 = 0;
        for (int seg = 31; seg >= 0; seg--) {
            if (acc + part[seg] >= target) {
                for (int bin = seg * 128 + 127;; bin--) {
                    int hc = hist[bin];
                    if (acc + hc >= target) { T1 = bin; break; }
                    acc += hc;
                }
                break;
            }
            acc += part[seg];
        }
        sT1 = T1; sA1 = acc;
    }
    __syncthreads();
    int T1 = sT1, target2 = 1000 - sA1;

    for (int i = tid; i < 4096; i += 1024) hist[i] = 0;
    __syncthreads();
    for (int a = tid; a < NA; a += 1024) {
        unsigned k = __float_as_uint(sc[a]);
        if ((int)(k >> 19) == T1) atomicAdd(&hist[(k >> 7) & 0xFFF], 1);
    }
    __syncthreads();
    if (tid < 32) { int t2 = 0; for (int i = 0; i < 128; i++) t2 += hist[tid * 128 + i]; part[tid] = t2; }
    __syncthreads();
    if (tid == 0) {
        int acc = 0, T2 = 0;
        for (int seg = 31; seg >= 0; seg--) {
            if (acc + part[seg] >= target2) {
                for (int bin = seg * 128 + 127;; bin--) {
                    int hc = hist[bin];
                    if (acc + hc >= target2) { T2 = bin; break; }
                    acc += hc;
                }
                break;
            }
            acc += part[seg];
        }
        sT2 = T2; cnt = 0;
    }
    __syncthreads();
    unsigned Tpre = ((unsigned)T1 << 12) | (unsigned)sT2;

    for (int a = tid; a < NA; a += 1024) {
        unsigned k = __float_as_uint(sc[a]);
        if ((k >> 7) >= Tpre) {
            int pos = atomicAdd(&cnt, 1);
            if (pos < 2048)
                cand[pos] = ((unsigned long long)(~k) << 32) | (unsigned)a;  // asc sort = desc score, asc idx
        }
    }
    __syncthreads();
    int c = min(cnt, 2048);
    for (int i = tid; i < 2048; i += 1024) if (i >= c) cand[i] = 0xFFFFFFFFFFFFFFFFULL;
    __syncthreads();

    // bitonic sort (ascending), 2048 elements
    for (int k2 = 2; k2 <= 2048; k2 <<= 1) {
        for (int s2 = k2 >> 1; s2 > 0; s2 >>= 1) {
            for (int e = tid; e < 2048; e += 1024) {
                int q = e ^ s2;
                if (q > e) {
                    bool asc = ((e & k2) == 0);
                    unsigned long long A = cand[e], Bv = cand[q];
                    if ((A > Bv) == asc) { cand[e] = Bv; cand[q] = A; }
                }
            }
            __syncthreads();
        }
    }

    // write top 1000 (+ padding to 1024)
    {
        float sco; int idx;
        if (tid < 1000) {
            unsigned long long v = cand[tid];
            idx = (int)(unsigned)(v & 0xFFFFFFFFu);
            sco = __uint_as_float(~(unsigned)(v >> 32));
        } else { sco = -1e30f; idx = 0; }
        g_topScore[b * 1024 + tid] = sco;
        g_topIdx[b * 1024 + tid]   = idx;
        int src = b * NA + idx;
        if (tid < 1000) {
            g_topBox[(b * 1024 + tid) * 4 + 0] = g_box[0][src];
            g_topBox[(b * 1024 + tid) * 4 + 1] = g_box[1][src];
            g_topBox[(b * 1024 + tid) * 4 + 2] = g_box[2][src];
            g_topBox[(b * 1024 + tid) * 4 + 3] = g_box[3][src];
        } else {
            g_topBox[(b * 1024 + tid) * 4 + 0] = 0.f;
            g_topBox[(b * 1024 + tid) * 4 + 1] = 0.f;
            g_topBox[(b * 1024 + tid) * 4 + 2] = 0.f;
            g_topBox[(b * 1024 + tid) * 4 + 3] = 0.f;
        }
    }
}

// ---------------- kernel 3: IoU bit-masks (fully parallel) ----------------
__global__ void __launch_bounds__(1024) mask_kernel() {
    int b = blockIdx.y, g = blockIdx.x, j = threadIdx.x;
    __shared__ float ib[32][4];
    if (j < 32) {
#pragma unroll
        for (int k = 0; k < 4; k++) ib[j][k] = g_topBox[(b * 1024 + g * 32 + j) * 4 + k];
    }
    __syncthreads();

    float x1 = g_topBox[(b * 1024 + j) * 4 + 0];
    float y1 = g_topBox[(b * 1024 + j) * 4 + 1];
    float x2 = g_topBox[(b * 1024 + j) * 4 + 2];
    float y2 = g_topBox[(b * 1024 + j) * 4 + 3];
    float area = fmaxf(x2 - x1, 0.f) * fmaxf(y2 - y1, 0.f);

    unsigned w = 0;
#pragma unroll
    for (int bb = 0; bb < 32; bb++) {
        int i = g * 32 + bb;
        float ix1 = ib[bb][0], iy1 = ib[bb][1], ix2 = ib[bb][2], iy2 = ib[bb][3];
        float iarea = fmaxf(ix2 - ix1, 0.f) * fmaxf(iy2 - iy1, 0.f);
        float iw = fmaxf(fminf(x2, ix2) - fmaxf(x1, ix1), 0.f);
        float ih = fmaxf(fminf(y2, iy2) - fmaxf(y1, iy1), 0.f);
        float inter = iw * ih;
        float uni = fmaxf(area + iarea - inter, 1e-8f);
        bool pred = (inter / uni > 0.3f) && (i < j);
        w |= ((unsigned)pred) << bb;
    }
    g_W[(b * 32 + g) * 1024 + j] = w;

    // intra-group 32x32 transpose (rows indexed by suppressor i)
    if ((j >> 5) == g) {
        int lane = j & 31;
        unsigned u = 0;
#pragma unroll
        for (int i = 0; i < 32; i++) {
            unsigned t = __ballot_sync(0xffffffffu, (w >> i) & 1u);
            if (lane == i) u = t;
        }
        g_U[(b * 32 + g) * 32 + lane] = u;
    }
}

// ---------------- kernel 4: greedy scan + output ----------------
__global__ void __launch_bounds__(1024) scan_kernel(float* __restrict__ out) {
    int b = blockIdx.x, j = threadIdx.x;
    int lane = j & 31, wid = j >> 5;
    __shared__ unsigned su[1024];
    __shared__ unsigned sm;

    float score = g_topScore[b * 1024 + j];
    bool alive = (j < 1000) && (score >= 0.05f);

    unsigned Tr[32];
#pragma unroll
    for (int g = 0; g < 32; g++) Tr[g] = g_W[(b * 32 + g) * 1024 + j];
    su[j] = g_U[b * 1024 + j];
    __syncthreads();

#pragma unroll
    for (int g = 0; g < 32; g++) {
        if (wid == g) {
            unsigned m = __ballot_sync(0xffffffffu, alive);
            if (lane == 0) {
#pragma unroll
                for (int bb = 0; bb < 32; bb++) {
                    unsigned take = (m >> bb) & 1u;
                    m &= ~(su[g * 32 + bb] & (0u - take));
                }
                sm = m;
            }
        }
        __syncthreads();
        unsigned m = sm;
        if (wid == g)      alive = (m >> lane) & 1u;
        else if (wid > g)  alive = alive && ((Tr[g] & m) == 0u);
        __syncthreads();
    }

    if (j < 1000) {
        int idx = g_topIdx[b * 1024 + j];
        float k = alive ? 1.0f : 0.0f;
        int src = b * NA + idx;
        out[b * 1000 + j] = score * k;                             // scores_post
        out[16000 + b * 1000 + j] = k * (float)g_cls[src];         // classes_post
#pragma unroll
        for (int q = 0; q < 5; q++)
            out[32000 + (b * 1000 + j) * 5 + q] = k * g_box[q][src]; // boxes_post
    }
}

// ---------------- launch ----------------
extern "C" void kernel_launch(void* const* d_in, const int* in_sizes, int n_in,
                              void* d_out, int out_size) {
    Ptrs P;
    for (int i = 0; i < 20; i++) P.p[i] = (const float*)d_in[i];

    decode_kernel<<<(NB * NA + 255) / 256, 256>>>(P);
    topk_kernel<<<NB, 1024>>>();
    mask_kernel<<<dim3(32, NB), 1024>>>();
    scan_kernel<<<NB, 1024>>>((float*)d_out);
}

// round 2
// speedup vs baseline: 1.4079x; 1.4079x over previous
#include <cuda_runtime.h>
#include <cuda_bf16.h>

#define NB 16
#define NA 49104

// ---------------- scratch (device globals; no allocation allowed) ----------------
__device__ float g_score[NB * NA];

__device__ float g_topScore[NB * 1024];
__device__ float g_topCls[NB * 1024];
__device__ float g_topTheta[NB * 1024];
__device__ float g_topBox[NB * 1024 * 4];

__device__ unsigned g_W[NB * 32 * 1024];  // [b][g][j] : bit i = iou(i=g*32+i, j)>thr && i<j
__device__ unsigned g_U[NB * 32 * 32];    // [b][g][i] : intra-group transpose (row = suppressor i)

struct Ptrs { const float* p[20]; };

__device__ __forceinline__ void level_of(int a, int& l, int& p, int& h, int& s) {
    if (a < 36864)      { l = 0; p = a;         h = 192; s = 8;   }
    else if (a < 46080) { l = 1; p = a - 36864; h = 96;  s = 16;  }
    else if (a < 48384) { l = 2; p = a - 46080; h = 48;  s = 32;  }
    else if (a < 48960) { l = 3; p = a - 48384; h = 24;  s = 64;  }
    else                { l = 4; p = a - 48960; h = 12;  s = 128; }
}

// ---------------- kernel 1: scores only (sigmoid monotone -> max on logits) ----------------
__global__ void __launch_bounds__(256) score_kernel(Ptrs in) {
    int t = blockIdx.x * blockDim.x + threadIdx.x;
    if (t >= NB * NA) return;
    int b = t / NA, a = t % NA;
    int l, p, h, s; level_of(a, l, p, h, s);
    int hh = h * h;
    const float* cls = in.p[l] + b * 15 * hh + p;
    float best = cls[0];
#pragma unroll
    for (int c = 1; c < 15; c++) best = fmaxf(best, cls[c * hh]);
    g_score[t] = 1.0f / (1.0f + expf(-best));
}

// ---------------- kernel 2: exact top-1000 (sorted) + winner decode ----------------
__global__ void __launch_bounds__(1024) topk_kernel(Ptrs in) {
    __shared__ int hist[4096];
    __shared__ unsigned long long cand[1024];
    __shared__ int part[32];
    __shared__ int cnt, sT, sAcc;

    int b = blockIdx.x, tid = threadIdx.x;
    int lane = tid & 31;
    const float* sc = g_score + b * NA;

    // ---- L1: top 12 bits, warp-aggregated atomics ----
    for (int i = tid; i < 4096; i += 1024) hist[i] = 0;
    __syncthreads();
    for (int it = 0; it < 48; it++) {
        int a = it * 1024 + tid;
        bool v = a < NA;
        unsigned bal = __ballot_sync(0xffffffffu, v);
        if (v) {
            int bin = (int)(__float_as_uint(sc[a]) >> 20);
            unsigned mm = __match_any_sync(bal, bin);
            if (lane == __ffs(mm) - 1) atomicAdd(&hist[bin], __popc(mm));
        }
    }
    __syncthreads();
    if (tid < 32) { int t2 = 0; for (int i = 0; i < 128; i++) t2 += hist[tid * 128 + i]; part[tid] = t2; }
    __syncthreads();
    if (tid == 0) {
        int target = 1000, acc = 0, T = 0;
        for (int seg = 31; seg >= 0; seg--) {
            if (acc + part[seg] >= target) {
                for (int bin = seg * 128 + 127;; bin--) {
                    int hc = hist[bin];
                    if (acc + hc >= target) { T = bin; break; }
                    acc += hc;
                }
                break;
            }
            acc += part[seg];
        }
        sT = T; sAcc = acc;
    }
    __syncthreads();
    int T1 = sT, target2 = 1000 - sAcc;

    // ---- L2: next 12 bits within bin T1 ----
    for (int i = tid; i < 4096; i += 1024) hist[i] = 0;
    __syncthreads();
    for (int a = tid; a < NA; a += 1024) {
        unsigned k = __float_as_uint(sc[a]);
        if ((int)(k >> 20) == T1) atomicAdd(&hist[(k >> 8) & 0xFFF], 1);
    }
    __syncthreads();
    if (tid < 32) { int t2 = 0; for (int i = 0; i < 128; i++) t2 += hist[tid * 128 + i]; part[tid] = t2; }
    __syncthreads();
    if (tid == 0) {
        int acc = 0, T = 0;
        for (int seg = 31; seg >= 0; seg--) {
            if (acc + part[seg] >= target2) {
                for (int bin = seg * 128 + 127;; bin--) {
                    int hc = hist[bin];
                    if (acc + hc >= target2) { T = bin; break; }
                    acc += hc;
                }
                break;
            }
            acc += part[seg];
        }
        sT = T; sAcc = acc;
    }
    __syncthreads();
    int T2 = sT, target3 = target2 - sAcc;
    int pre24 = (T1 << 12) | T2;

    // ---- L3: last 8 bits -> exact 32-bit threshold ----
    for (int i = tid; i < 256; i += 1024) hist[i] = 0;
    __syncthreads();
    for (int a = tid; a < NA; a += 1024) {
        unsigned k = __float_as_uint(sc[a]);
        if ((int)(k >> 8) == pre24) atomicAdd(&hist[k & 0xFF], 1);
    }
    __syncthreads();
    if (tid == 0) {
        int acc = 0, T = 0;
        for (int bin = 255;; bin--) {
            int hc = hist[bin];
            if (acc + hc >= target3) { T = bin; break; }
            acc += hc;
        }
        sT = T; cnt = 0;
    }
    __syncthreads();
    unsigned Tbits = ((unsigned)pre24 << 8) | (unsigned)sT;

    // ---- collect candidates (count in [1000, 1000+dups], capped 1024) ----
    for (int a = tid; a < NA; a += 1024) {
        unsigned k = __float_as_uint(sc[a]);
        if (k >= Tbits) {
            int pos = atomicAdd(&cnt, 1);
            if (pos < 1024)
                cand[pos] = ((unsigned long long)(~k) << 32) | (unsigned)a;  // asc = desc score, asc idx
        }
    }
    __syncthreads();
    int c = min(cnt, 1024);
    if (tid >= c) cand[tid] = 0xFFFFFFFFFFFFFFFFULL;
    __syncthreads();

    // ---- bitonic sort 1024 (warp-local phases barrier-free) ----
    // k = 2..32: partners within warp -> __syncwarp only
    for (int k2 = 2; k2 <= 32; k2 <<= 1) {
        for (int s2 = k2 >> 1; s2 > 0; s2 >>= 1) {
            __syncwarp();
            int q = tid ^ s2;
            if (q > tid) {
                bool asc = ((tid & k2) == 0);
                unsigned long long A = cand[tid], Bv = cand[q];
                if ((A > Bv) == asc) { cand[tid] = Bv; cand[q] = A; }
            }
        }
    }
    for (int k2 = 64; k2 <= 1024; k2 <<= 1) {
        for (int s2 = k2 >> 1; s2 > 0; s2 >>= 1) {
            if (s2 >= 16) __syncthreads(); else __syncwarp();
            int q = tid ^ s2;
            if (q > tid) {
                bool asc = ((tid & k2) == 0);
                unsigned long long A = cand[tid], Bv = cand[q];
                if ((A > Bv) == asc) { cand[tid] = Bv; cand[q] = A; }
            }
        }
    }
    __syncthreads();

    // ---- winner decode (class / theta / box from raw inputs) ----
    int o = b * 1024 + tid;
    if (tid < 1000) {
        unsigned long long v = cand[tid];
        int a = (int)(unsigned)(v & 0xFFFFFFFFu);
        float score = __uint_as_float(~(unsigned)(v >> 32));

        int l, p, h, s; level_of(a, l, p, h, s);
        int hh = h * h;
        const float* cls = in.p[l]      + b * 15 * hh + p;
        const float* reg = in.p[5 + l]  + b * 5  * hh + p;
        const float* tcp = in.p[10 + l] + b * 18 * hh + p;
        const float* trp = in.p[15 + l] + b * hh + p;

        float best = cls[0]; int bc = 0;
#pragma unroll
        for (int cc = 1; cc < 15; cc++) { float vv = cls[cc * hh]; if (vv > best) { best = vv; bc = cc; } }
        float tb = tcp[0]; int ta = 0;
#pragma unroll
        for (int cc = 1; cc < 18; cc++) { float vv = tcp[cc * hh]; if (vv > tb) { tb = vv; ta = cc; } }
        float theta = (float)(ta + 1) * 10.0f + trp[0];

        float fs = (float)s;
        int col = p % h, row = p / h;
        float x = (float)col * fs + (float)(s / 2);
        float y = (float)row * fs + (float)(s / 2);

        g_topScore[o] = score;
        g_topCls[o]   = (float)(bc + 1);
        g_topTheta[o] = theta;
        g_topBox[o * 4 + 0] = x - reg[0] * fs;
        g_topBox[o * 4 + 1] = y - reg[hh] * fs;
        g_topBox[o * 4 + 2] = x + reg[2 * hh] * fs;
        g_topBox[o * 4 + 3] = y + reg[3 * hh] * fs;
    } else {
        g_topScore[o] = -1e30f;
        g_topCls[o] = 0.f; g_topTheta[o] = 0.f;
        g_topBox[o * 4 + 0] = 0.f; g_topBox[o * 4 + 1] = 0.f;
        g_topBox[o * 4 + 2] = 0.f; g_topBox[o * 4 + 3] = 0.f;
    }
}

// ---------------- kernel 3: IoU bit-masks (fully parallel) ----------------
__global__ void __launch_bounds__(1024) mask_kernel() {
    int b = blockIdx.y, g = blockIdx.x, j = threadIdx.x;
    __shared__ float ib[32][4];
    if (j < 32) {
#pragma unroll
        for (int k = 0; k < 4; k++) ib[j][k] = g_topBox[(b * 1024 + g * 32 + j) * 4 + k];
    }
    __syncthreads();

    float x1 = g_topBox[(b * 1024 + j) * 4 + 0];
    float y1 = g_topBox[(b * 1024 + j) * 4 + 1];
    float x2 = g_topBox[(b * 1024 + j) * 4 + 2];
    float y2 = g_topBox[(b * 1024 + j) * 4 + 3];
    float area = fmaxf(x2 - x1, 0.f) * fmaxf(y2 - y1, 0.f);

    unsigned w = 0;
#pragma unroll
    for (int bb = 0; bb < 32; bb++) {
        int i = g * 32 + bb;
        float ix1 = ib[bb][0], iy1 = ib[bb][1], ix2 = ib[bb][2], iy2 = ib[bb][3];
        float iarea = fmaxf(ix2 - ix1, 0.f) * fmaxf(iy2 - iy1, 0.f);
        float iw = fmaxf(fminf(x2, ix2) - fmaxf(x1, ix1), 0.f);
        float ih = fmaxf(fminf(y2, iy2) - fmaxf(y1, iy1), 0.f);
        float inter = iw * ih;
        float uni = fmaxf(area + iarea - inter, 1e-8f);
        bool pred = (inter > 0.3f * uni) && (i < j);
        w |= ((unsigned)pred) << bb;
    }
    g_W[(b * 32 + g) * 1024 + j] = w;

    if ((j >> 5) == g) {
        int lane = j & 31;
        unsigned u = 0;
#pragma unroll
        for (int i = 0; i < 32; i++) {
            unsigned t = __ballot_sync(0xffffffffu, (w >> i) & 1u);
            if (lane == i) u = t;
        }
        g_U[(b * 32 + g) * 32 + lane] = u;
    }
}

// ---------------- kernel 4: greedy scan + output ----------------
__global__ void __launch_bounds__(1024) scan_kernel(float* __restrict__ out) {
    int b = blockIdx.x, j = threadIdx.x;
    int lane = j & 31, wid = j >> 5;
    __shared__ unsigned su[1024];
    __shared__ unsigned sm_arr[32];

    float score = g_topScore[b * 1024 + j];
    bool alive = (j < 1000) && (score >= 0.05f);

    unsigned Tr[32];
#pragma unroll
    for (int g = 0; g < 32; g++) Tr[g] = g_W[(b * 32 + g) * 1024 + j];
    unsigned su_own = g_U[b * 1024 + j];
    su[j] = su_own;
    // nonzero-suppressor-row mask for my warp's group (most rows are 0 -> skip)
    unsigned nzm = __ballot_sync(0xffffffffu, su_own != 0u);
    __syncthreads();

#pragma unroll
    for (int g = 0; g < 32; g++) {
        if (wid == g) {
            unsigned m = __ballot_sync(0xffffffffu, alive);
            if (lane == 0) {
                unsigned todo = nzm & m;
                while (todo) {
                    int bb = __ffs(todo) - 1;
                    m &= ~su[g * 32 + bb];       // row bb has only bits > bb
                    todo &= todo - 1;
                    todo &= m;                   // drop rows that just died
                }
                sm_arr[g] = m;
            }
        }
        __syncthreads();                          // single barrier per group
        unsigned m = sm_arr[g];
        if (wid == g)      alive = (m >> lane) & 1u;
        else if (wid > g)  alive = alive && ((Tr[g] & m) == 0u);
    }

    if (j < 1000) {
        float k = alive ? 1.0f : 0.0f;
        int o = b * 1024 + j;
        out[b * 1000 + j] = score * k;                          // scores_post
        out[16000 + b * 1000 + j] = k * g_topCls[o];            // classes_post
        int base = 32000 + (b * 1000 + j) * 5;
        out[base + 0] = k * g_topBox[o * 4 + 0];
        out[base + 1] = k * g_topBox[o * 4 + 1];
        out[base + 2] = k * g_topBox[o * 4 + 2];
        out[base + 3] = k * g_topBox[o * 4 + 3];
        out[base + 4] = k * g_topTheta[o];
    }
}

// ---------------- launch ----------------
extern "C" void kernel_launch(void* const* d_in, const int* in_sizes, int n_in,
                              void* d_out, int out_size) {
    Ptrs P;
    for (int i = 0; i < 20; i++) P.p[i] = (const float*)d_in[i];

    score_kernel<<<(NB * NA + 255) / 256, 256>>>(P);
    topk_kernel<<<NB, 1024>>>(P);
    mask_kernel<<<dim3(32, NB), 1024>>>();
    scan_kernel<<<NB, 1024>>>((float*)d_out);
}